// round 15
// baseline (speedup 1.0000x reference)
#include <cuda_runtime.h>
#include <cuda_bf16.h>
#include <cstdint>

// Problem constants
constexpr int NB  = 16;    // batch
constexpr int LQ  = 256;
constexpr int LK  = 256;
constexpr int H   = 256;   // hidden = DQ = DK = DV

// Scratch (no cudaMalloc allowed)
__device__ float g_q[NB * LQ * H];
__device__ float g_k[NB * LK * H];
__device__ float g_s[NB * LQ * LK];   // raw scores

__device__ __forceinline__ uint32_t smem_u32(const void* p) {
    uint32_t a;
    asm("{ .reg .u64 t; cvta.to.shared.u64 t, %1; cvt.u32.u64 %0, t; }"
        : "=r"(a) : "l"(p));
    return a;
}

__device__ __forceinline__ void ldsm_x4(uint32_t* r, uint32_t addr) {
    asm volatile("ldmatrix.sync.aligned.m8n8.x4.shared.b16 {%0,%1,%2,%3}, [%4];"
        : "=r"(r[0]), "=r"(r[1]), "=r"(r[2]), "=r"(r[3]) : "r"(addr));
}
__device__ __forceinline__ void ldsm_x2_trans(uint32_t* r, uint32_t addr) {
    asm volatile("ldmatrix.sync.aligned.m8n8.x2.trans.shared.b16 {%0,%1}, [%2];"
        : "=r"(r[0]), "=r"(r[1]) : "r"(addr));
}
__device__ __forceinline__ void mma_bf16(float* c, const uint32_t* a, const uint32_t* b) {
    asm volatile(
        "mma.sync.aligned.m16n8k16.row.col.f32.bf16.bf16.f32 "
        "{%0,%1,%2,%3}, {%4,%5,%6,%7}, {%8,%9}, {%0,%1,%2,%3};"
        : "+f"(c[0]), "+f"(c[1]), "+f"(c[2]), "+f"(c[3])
        : "r"(a[0]), "r"(a[1]), "r"(a[2]), "r"(a[3]), "r"(b[0]), "r"(b[1]));
}

__device__ __forceinline__ uint32_t pack_hi(float x, float y) {
    __nv_bfloat162 v;
    v.x = __float2bfloat16(x);
    v.y = __float2bfloat16(y);
    return *(uint32_t*)&v;
}
__device__ __forceinline__ uint32_t pack_lo(float x, float y) {
    __nv_bfloat16 hx = __float2bfloat16(x);
    __nv_bfloat16 hy = __float2bfloat16(y);
    __nv_bfloat162 v;
    v.x = __float2bfloat16(x - __bfloat162float(hx));
    v.y = __float2bfloat16(y - __bfloat162float(hy));
    return *(uint32_t*)&v;
}

// f16x2 helpers (score kernel)
__device__ __forceinline__ uint32_t pack_f16x2(float lo, float hi) {
    uint32_t r;
    asm("cvt.rn.f16x2.f32 %0, %1, %2;" : "=r"(r) : "f"(hi), "f"(lo)); // a->hi, b->lo
    return r;
}
__device__ __forceinline__ uint32_t hadd2(uint32_t a, uint32_t b) {
    uint32_t r;
    asm("add.rn.f16x2 %0, %1, %2;" : "=r"(r) : "r"(a), "r"(b));
    return r;
}
__device__ __forceinline__ uint32_t tanh2(uint32_t x) {
    uint32_t r;
    asm("tanh.approx.f16x2 %0, %1;" : "=r"(r) : "r"(x));
    return r;
}
__device__ __forceinline__ float2 unpack_f16x2(uint32_t p) {
    float lo, hi;
    asm("{ .reg .b16 l, h;\n\t"
        "mov.b32 {l, h}, %2;\n\t"
        "cvt.f32.f16 %0, l;\n\t"
        "cvt.f32.f16 %1, h; }"
        : "=f"(lo), "=f"(hi) : "r"(p));
    return make_float2(lo, hi);
}

// ===========================================================================
// Kernel 1: tensor-core projections via mma.sync bf16x3 split (fused convert)
// CTA: 128x128 tile, BK=32, 512 threads. Single wave (128 CTAs).
// Register double-buffered staging. (Unchanged best config.)
// ===========================================================================
constexpr int PROJ_BM = 128, PROJ_BN = 128, PROJ_BK = 32;
constexpr int SP_A = 72, SP_B = 136;
constexpr int SM_AH_OFF = 0;
constexpr int SM_AL_OFF = SM_AH_OFF + PROJ_BM * SP_A;
constexpr int SM_BH_OFF = SM_AL_OFF + PROJ_BM * SP_A;
constexpr int SM_BL_OFF = SM_BH_OFF + PROJ_BK * SP_B;
constexpr int PROJ_SMEM_BYTES = (SM_BL_OFF + PROJ_BK * SP_B) * 2;

__global__ __launch_bounds__(512) void proj_mma_kernel(
    const float* __restrict__ Aq, const float* __restrict__ Ak,
    const float* __restrict__ Wq, const float* __restrict__ Wk,
    const int* __restrict__ valid_lens)
{
    extern __shared__ __nv_bfloat16 smp[];
    __nv_bfloat16* sAh = smp + SM_AH_OFF;
    __nv_bfloat16* sAl = smp + SM_AL_OFF;
    __nv_bfloat16* sBh = smp + SM_BH_OFF;
    __nv_bfloat16* sBl = smp + SM_BL_OFF;

    const int z  = blockIdx.z;
    const int m0 = blockIdx.x * PROJ_BM;
    const int n0 = blockIdx.y * PROJ_BN;

    if (z) {
        const int b = m0 >> 8;
        if ((m0 & 255) >= __ldg(&valid_lens[b])) return;
    }

    const float* A = z ? Ak : Aq;
    const float* W = z ? Wk : Wq;
    float*       C = z ? g_k : g_q;

    const int t    = threadIdx.x;
    const int lane = t & 31;
    const int warp = t >> 5;
    const int wm   = (warp & 3) * 32;
    const int wn   = (warp >> 2) * 32;

    float acc[2][4][4] = {};

    float4 pa[2], pb[2];
    #pragma unroll
    for (int i = 0; i < 2; i++) {
        const int idx = t + i * 512;
        pa[i] = *(const float4*)&A[((m0 + (idx >> 3)) * H) + ((idx & 7) << 2)];
        pb[i] = *(const float4*)&W[((idx >> 5) * H) + n0 + ((idx & 31) << 2)];
    }

    #pragma unroll
    for (int chunk = 0; chunk < H / PROJ_BK; chunk++) {
        #pragma unroll
        for (int i = 0; i < 2; i++) {
            const int idx = t + i * 512;
            {
                const int r = idx >> 3;
                const int c = (idx & 7) << 2;
                float4 v = pa[i];
                *(uint32_t*)&sAh[r * SP_A + c]     = pack_hi(v.x, v.y);
                *(uint32_t*)&sAh[r * SP_A + c + 2] = pack_hi(v.z, v.w);
                *(uint32_t*)&sAl[r * SP_A + c]     = pack_lo(v.x, v.y);
                *(uint32_t*)&sAl[r * SP_A + c + 2] = pack_lo(v.z, v.w);
            }
            {
                const int kr = idx >> 5;
                const int nc = (idx & 31) << 2;
                float4 v = pb[i];
                *(uint32_t*)&sBh[kr * SP_B + nc]     = pack_hi(v.x, v.y);
                *(uint32_t*)&sBh[kr * SP_B + nc + 2] = pack_hi(v.z, v.w);
                *(uint32_t*)&sBl[kr * SP_B + nc]     = pack_lo(v.x, v.y);
                *(uint32_t*)&sBl[kr * SP_B + nc + 2] = pack_lo(v.z, v.w);
            }
        }
        __syncthreads();

        if (chunk + 1 < H / PROJ_BK) {
            const int k0n = (chunk + 1) * PROJ_BK;
            #pragma unroll
            for (int i = 0; i < 2; i++) {
                const int idx = t + i * 512;
                pa[i] = *(const float4*)&A[((m0 + (idx >> 3)) * H) + k0n + ((idx & 7) << 2)];
                pb[i] = *(const float4*)&W[((k0n + (idx >> 5)) * H) + n0 + ((idx & 31) << 2)];
            }
        }

        #pragma unroll
        for (int ks = 0; ks < 2; ks++) {
            const int kb = ks * 16;

            uint32_t ah[2][4], al[2][4];
            #pragma unroll
            for (int mt = 0; mt < 2; mt++) {
                const int row = wm + mt * 16 + (lane & 15);
                const int kc  = kb + ((lane >> 4) << 3);
                ldsm_x4(ah[mt], smem_u32(&sAh[row * SP_A + kc]));
                ldsm_x4(al[mt], smem_u32(&sAl[row * SP_A + kc]));
            }
            #pragma unroll
            for (int nt = 0; nt < 4; nt++) {
                uint32_t bh[2], bl[2];
                const int krow  = kb + (lane & 15);
                const int nbase = wn + nt * 8;
                ldsm_x2_trans(bh, smem_u32(&sBh[krow * SP_B + nbase]));
                ldsm_x2_trans(bl, smem_u32(&sBl[krow * SP_B + nbase]));
                #pragma unroll
                for (int mt = 0; mt < 2; mt++) {
                    mma_bf16(acc[mt][nt], ah[mt], bh);
                    mma_bf16(acc[mt][nt], al[mt], bh);
                    mma_bf16(acc[mt][nt], ah[mt], bl);
                }
            }
        }
        __syncthreads();
    }

    #pragma unroll
    for (int mt = 0; mt < 2; mt++) {
        const int r0 = m0 + wm + mt * 16 + (lane >> 2);
        #pragma unroll
        for (int nt = 0; nt < 4; nt++) {
            const int c0 = n0 + wn + nt * 8 + (lane & 3) * 2;
            *(float2*)&C[r0 * H + c0]       = make_float2(acc[mt][nt][0], acc[mt][nt][1]);
            *(float2*)&C[(r0 + 8) * H + c0] = make_float2(acc[mt][nt][2], acc[mt][nt][3]);
        }
    }
}

// ---------------------------------------------------------------------------
// Kernel 2: scores via full f16x2 path
// smem q/k staged as f16 (26KB -> 8 CTAs/SM); inner loop: LDS.64 + HADD2 +
// tanh.approx.f16x2 + fp32 FFMA accumulate (w stays fp32).
// One CTA per (j-tile, b, q-tile); CTAs beyond valid_len exit instantly.
// ---------------------------------------------------------------------------
__global__ __launch_bounds__(128, 8) void score_kernel(
    const int* __restrict__ valid_lens, const float* __restrict__ w_v)
{
    constexpr int QI = 16;
    constexpr int KJ = 32;
    constexpr int HPH = H + 4;   // halves; stride 260 halves = 130 words ≡ 2 mod 32

    const int jt = blockIdx.x;
    const int b  = blockIdx.y;
    const int q0 = blockIdx.z * QI;
    const int j0 = jt * KJ;

    const int vl = __ldg(&valid_lens[b]);
    if (j0 >= vl) return;

    extern __shared__ char smraw[];
    __half* sq = (__half*)smraw;                 // QI * HPH halves
    __half* sk = sq + QI * HPH;                  // KJ * HPH halves
    float*  sw = (float*)(sk + KJ * HPH);        // H floats

    const int t    = threadIdx.x;
    const int lane = t & 31;
    const int warp = t >> 5;

    // Stage q (convert fp32 -> f16 pairs)
    for (int idx = t; idx < QI * (H / 4); idx += 128) {
        const int i  = idx >> 6;
        const int hc = (idx & 63) << 2;
        float4 v = *(const float4*)&g_q[(b * LQ + q0 + i) * H + hc];
        uint2 p = make_uint2(pack_f16x2(v.x, v.y), pack_f16x2(v.z, v.w));
        *(uint2*)&sq[i * HPH + hc] = p;
    }
    // Stage k
    for (int idx = t; idx < KJ * (H / 4); idx += 128) {
        const int j  = idx >> 6;
        const int hc = (idx & 63) << 2;
        float4 v = *(const float4*)&g_k[(b * LK + j0 + j) * H + hc];
        uint2 p = make_uint2(pack_f16x2(v.x, v.y), pack_f16x2(v.z, v.w));
        *(uint2*)&sk[j * HPH + hc] = p;
    }
    if (t < H / 4) *(float4*)&sw[t * 4] = *(const float4*)&w_v[t * 4];
    __syncthreads();

    float a0 = 0.f, a1 = 0.f, a2 = 0.f, a3 = 0.f;
    const __half* qp0 = &sq[(warp * 4 + 0) * HPH];
    const __half* qp1 = &sq[(warp * 4 + 1) * HPH];
    const __half* qp2 = &sq[(warp * 4 + 2) * HPH];
    const __half* qp3 = &sq[(warp * 4 + 3) * HPH];
    const __half* kp  = &sk[lane * HPH];

    #pragma unroll 2
    for (int h = 0; h < H; h += 4) {
        uint2 kq = *(const uint2*)&kp[h];        // k[h..h+3] as 2x f16x2
        float4 w4 = *(const float4*)&sw[h];

        {
            uint2 qq = *(const uint2*)&qp0[h];
            float2 t01 = unpack_f16x2(tanh2(hadd2(qq.x, kq.x)));
            float2 t23 = unpack_f16x2(tanh2(hadd2(qq.y, kq.y)));
            a0 += w4.x * t01.x; a0 += w4.y * t01.y;
            a0 += w4.z * t23.x; a0 += w4.w * t23.y;
        }
        {
            uint2 qq = *(const uint2*)&qp1[h];
            float2 t01 = unpack_f16x2(tanh2(hadd2(qq.x, kq.x)));
            float2 t23 = unpack_f16x2(tanh2(hadd2(qq.y, kq.y)));
            a1 += w4.x * t01.x; a1 += w4.y * t01.y;
            a1 += w4.z * t23.x; a1 += w4.w * t23.y;
        }
        {
            uint2 qq = *(const uint2*)&qp2[h];
            float2 t01 = unpack_f16x2(tanh2(hadd2(qq.x, kq.x)));
            float2 t23 = unpack_f16x2(tanh2(hadd2(qq.y, kq.y)));
            a2 += w4.x * t01.x; a2 += w4.y * t01.y;
            a2 += w4.z * t23.x; a2 += w4.w * t23.y;
        }
        {
            uint2 qq = *(const uint2*)&qp3[h];
            float2 t01 = unpack_f16x2(tanh2(hadd2(qq.x, kq.x)));
            float2 t23 = unpack_f16x2(tanh2(hadd2(qq.y, kq.y)));
            a3 += w4.x * t01.x; a3 += w4.y * t01.y;
            a3 += w4.z * t23.x; a3 += w4.w * t23.y;
        }
    }

    const int rbase = b * LQ + q0 + warp * 4;
    g_s[(rbase + 0) * LK + j0 + lane] = a0;
    g_s[(rbase + 1) * LK + j0 + lane] = a1;
    g_s[(rbase + 2) * LK + j0 + lane] = a2;
    g_s[(rbase + 3) * LK + j0 + lane] = a3;
}

// ---------------------------------------------------------------------------
// Kernel 3: masked softmax over j + out = P @ V
// QI=16 rows per CTA, 256 threads. Stages only columns j < valid_len.
// ---------------------------------------------------------------------------
__global__ __launch_bounds__(256) void softpv_kernel(
    const float* __restrict__ values, const int* __restrict__ valid_lens,
    float* __restrict__ out)
{
    constexpr int QI = 16;
    __shared__ float sp[QI * LK];

    const int b    = blockIdx.x;
    const int q0   = blockIdx.y * QI;
    const int t    = threadIdx.x;
    const int lane = t & 31;
    const int warp = t >> 5;          // 0..7

    const int vl = valid_lens[b];

    for (int idx = t; idx < QI * (LK / 4); idx += 256) {
        const int i  = idx >> 6;
        const int jc = (idx & 63) << 2;
        if (jc < vl)
            *(float4*)&sp[i * LK + jc] =
                *(const float4*)&g_s[(b * LQ + q0 + i) * LK + jc];
    }
    __syncthreads();

    #pragma unroll
    for (int rr = 0; rr < 2; rr++) {
        const int r = warp + rr * 8;
        float* row = &sp[r * LK];

        float m = -1e30f;
        for (int j = lane; j < LK; j += 32) {
            float s = (j < vl) ? row[j] : -1e30f;
            m = fmaxf(m, s);
        }
        #pragma unroll
        for (int o = 16; o; o >>= 1) m = fmaxf(m, __shfl_xor_sync(0xffffffffu, m, o));

        float ssum = 0.f;
        for (int j = lane; j < LK; j += 32) {
            float e = (j < vl) ? __expf(row[j] - m) : 0.f;
            row[j] = e;
            ssum += e;
        }
        #pragma unroll
        for (int o = 16; o; o >>= 1) ssum += __shfl_xor_sync(0xffffffffu, ssum, o);

        const float inv = 1.0f / ssum;
        for (int j = lane; j < LK; j += 32) row[j] *= inv;
    }
    __syncthreads();

    const int ig = (t >> 6) * 4;        // 0,4,8,12
    const int v0 = (t & 63) * 4;        // 0..252
    float acc[4][4] = {};
    const float* vb = &values[b * LK * H];

    const int jend = min(LK, (vl + 3) & ~3);
    for (int j = 0; j < jend; j += 4) {
        float vvf[4][4];
        #pragma unroll
        for (int jj = 0; jj < 4; jj++) {
            float4 tmp = *(const float4*)&vb[(j + jj) * H + v0];
            vvf[jj][0] = tmp.x; vvf[jj][1] = tmp.y; vvf[jj][2] = tmp.z; vvf[jj][3] = tmp.w;
        }
        #pragma unroll
        for (int r = 0; r < 4; r++) {
            float4 p = *(const float4*)&sp[(ig + r) * LK + j];
            #pragma unroll
            for (int c = 0; c < 4; c++) {
                acc[r][c] += p.x * vvf[0][c];
                acc[r][c] += p.y * vvf[1][c];
                acc[r][c] += p.z * vvf[2][c];
                acc[r][c] += p.w * vvf[3][c];
            }
        }
    }

    #pragma unroll
    for (int r = 0; r < 4; r++) {
        float4 o = make_float4(acc[r][0], acc[r][1], acc[r][2], acc[r][3]);
        *(float4*)&out[(b * LQ + q0 + ig + r) * H + v0] = o;
    }
}

// ---------------------------------------------------------------------------
extern "C" void kernel_launch(void* const* d_in, const int* in_sizes, int n_in,
                              void* d_out, int out_size) {
    (void)in_sizes; (void)n_in; (void)out_size;
    const float* queries = (const float*)d_in[0];
    const float* keys    = (const float*)d_in[1];
    const float* values  = (const float*)d_in[2];
    const int*   vlens   = (const int*)d_in[3];
    const float* Wq      = (const float*)d_in[4];
    const float* Wk      = (const float*)d_in[5];
    const float* wv      = (const float*)d_in[6];
    float* out = (float*)d_out;

    cudaFuncSetAttribute(proj_mma_kernel,
                         cudaFuncAttributeMaxDynamicSharedMemorySize, PROJ_SMEM_BYTES);
    dim3 pg((NB * LQ) / PROJ_BM, H / PROJ_BN, 2);   // 128 CTAs
    proj_mma_kernel<<<pg, 512, PROJ_SMEM_BYTES>>>(queries, keys, Wq, Wk, vlens);

    constexpr int QI = 16, KJ = 32, HPH = H + 4;
    constexpr int SMEM = (QI * HPH + KJ * HPH) * 2 + H * 4;   // ~26KB
    cudaFuncSetAttribute(score_kernel, cudaFuncAttributeMaxDynamicSharedMemorySize, SMEM);
    dim3 sg(LK / KJ, NB, LQ / QI);   // j-tile fastest
    score_kernel<<<sg, 128, SMEM>>>(vlens, wv);

    dim3 og(NB, LQ / 16);            // 256 CTAs
    softpv_kernel<<<og, 256>>>(values, vlens, out);
}

// round 16
// speedup vs baseline: 1.1228x; 1.1228x over previous
#include <cuda_runtime.h>
#include <cuda_bf16.h>
#include <cstdint>

// Problem constants
constexpr int NB  = 16;    // batch
constexpr int LQ  = 256;
constexpr int LK  = 256;
constexpr int H   = 256;   // hidden = DQ = DK = DV

// Scratch (no cudaMalloc allowed)
__device__ float g_q[NB * LQ * H];
__device__ float g_k[NB * LK * H];
__device__ float g_s[NB * LQ * LK];   // raw scores

__device__ __forceinline__ uint32_t smem_u32(const void* p) {
    uint32_t a;
    asm("{ .reg .u64 t; cvta.to.shared.u64 t, %1; cvt.u32.u64 %0, t; }"
        : "=r"(a) : "l"(p));
    return a;
}

__device__ __forceinline__ void ldsm_x4(uint32_t* r, uint32_t addr) {
    asm volatile("ldmatrix.sync.aligned.m8n8.x4.shared.b16 {%0,%1,%2,%3}, [%4];"
        : "=r"(r[0]), "=r"(r[1]), "=r"(r[2]), "=r"(r[3]) : "r"(addr));
}
__device__ __forceinline__ void ldsm_x2_trans(uint32_t* r, uint32_t addr) {
    asm volatile("ldmatrix.sync.aligned.m8n8.x2.trans.shared.b16 {%0,%1}, [%2];"
        : "=r"(r[0]), "=r"(r[1]) : "r"(addr));
}
__device__ __forceinline__ void mma_bf16(float* c, const uint32_t* a, const uint32_t* b) {
    asm volatile(
        "mma.sync.aligned.m16n8k16.row.col.f32.bf16.bf16.f32 "
        "{%0,%1,%2,%3}, {%4,%5,%6,%7}, {%8,%9}, {%0,%1,%2,%3};"
        : "+f"(c[0]), "+f"(c[1]), "+f"(c[2]), "+f"(c[3])
        : "r"(a[0]), "r"(a[1]), "r"(a[2]), "r"(a[3]), "r"(b[0]), "r"(b[1]));
}

__device__ __forceinline__ uint32_t pack_hi(float x, float y) {
    __nv_bfloat162 v;
    v.x = __float2bfloat16(x);
    v.y = __float2bfloat16(y);
    return *(uint32_t*)&v;
}
__device__ __forceinline__ uint32_t pack_lo(float x, float y) {
    __nv_bfloat16 hx = __float2bfloat16(x);
    __nv_bfloat16 hy = __float2bfloat16(y);
    __nv_bfloat162 v;
    v.x = __float2bfloat16(x - __bfloat162float(hx));
    v.y = __float2bfloat16(y - __bfloat162float(hy));
    return *(uint32_t*)&v;
}

// f16x2 helpers (score kernel)
__device__ __forceinline__ uint32_t pack_f16x2(float lo, float hi) {
    uint32_t r;
    asm("cvt.rn.f16x2.f32 %0, %1, %2;" : "=r"(r) : "f"(hi), "f"(lo)); // a->hi, b->lo
    return r;
}
__device__ __forceinline__ uint32_t tanh2(uint32_t x) {
    uint32_t r;
    asm("tanh.approx.f16x2 %0, %1;" : "=r"(r) : "r"(x));
    return r;
}
__device__ __forceinline__ float2 unpack_f16x2(uint32_t p) {
    float lo, hi;
    asm("{ .reg .b16 l, h;\n\t"
        "mov.b32 {l, h}, %2;\n\t"
        "cvt.f32.f16 %0, l;\n\t"
        "cvt.f32.f16 %1, h; }"
        : "=f"(lo), "=f"(hi) : "r"(p));
    return make_float2(lo, hi);
}

// ===========================================================================
// Kernel 1: tensor-core projections via mma.sync bf16x3 split (fused convert)
// CTA: 128x128 tile, BK=32, 512 threads. Single wave (128 CTAs).
// Register double-buffered staging. (Unchanged best config, 15.7us.)
// ===========================================================================
constexpr int PROJ_BM = 128, PROJ_BN = 128, PROJ_BK = 32;
constexpr int SP_A = 72, SP_B = 136;
constexpr int SM_AH_OFF = 0;
constexpr int SM_AL_OFF = SM_AH_OFF + PROJ_BM * SP_A;
constexpr int SM_BH_OFF = SM_AL_OFF + PROJ_BM * SP_A;
constexpr int SM_BL_OFF = SM_BH_OFF + PROJ_BK * SP_B;
constexpr int PROJ_SMEM_BYTES = (SM_BL_OFF + PROJ_BK * SP_B) * 2;

__global__ __launch_bounds__(512) void proj_mma_kernel(
    const float* __restrict__ Aq, const float* __restrict__ Ak,
    const float* __restrict__ Wq, const float* __restrict__ Wk,
    const int* __restrict__ valid_lens)
{
    extern __shared__ __nv_bfloat16 smp[];
    __nv_bfloat16* sAh = smp + SM_AH_OFF;
    __nv_bfloat16* sAl = smp + SM_AL_OFF;
    __nv_bfloat16* sBh = smp + SM_BH_OFF;
    __nv_bfloat16* sBl = smp + SM_BL_OFF;

    const int z  = blockIdx.z;
    const int m0 = blockIdx.x * PROJ_BM;
    const int n0 = blockIdx.y * PROJ_BN;

    if (z) {
        const int b = m0 >> 8;
        if ((m0 & 255) >= __ldg(&valid_lens[b])) return;
    }

    const float* A = z ? Ak : Aq;
    const float* W = z ? Wk : Wq;
    float*       C = z ? g_k : g_q;

    const int t    = threadIdx.x;
    const int lane = t & 31;
    const int warp = t >> 5;
    const int wm   = (warp & 3) * 32;
    const int wn   = (warp >> 2) * 32;

    float acc[2][4][4] = {};

    float4 pa[2], pb[2];
    #pragma unroll
    for (int i = 0; i < 2; i++) {
        const int idx = t + i * 512;
        pa[i] = *(const float4*)&A[((m0 + (idx >> 3)) * H) + ((idx & 7) << 2)];
        pb[i] = *(const float4*)&W[((idx >> 5) * H) + n0 + ((idx & 31) << 2)];
    }

    #pragma unroll
    for (int chunk = 0; chunk < H / PROJ_BK; chunk++) {
        #pragma unroll
        for (int i = 0; i < 2; i++) {
            const int idx = t + i * 512;
            {
                const int r = idx >> 3;
                const int c = (idx & 7) << 2;
                float4 v = pa[i];
                *(uint32_t*)&sAh[r * SP_A + c]     = pack_hi(v.x, v.y);
                *(uint32_t*)&sAh[r * SP_A + c + 2] = pack_hi(v.z, v.w);
                *(uint32_t*)&sAl[r * SP_A + c]     = pack_lo(v.x, v.y);
                *(uint32_t*)&sAl[r * SP_A + c + 2] = pack_lo(v.z, v.w);
            }
            {
                const int kr = idx >> 5;
                const int nc = (idx & 31) << 2;
                float4 v = pb[i];
                *(uint32_t*)&sBh[kr * SP_B + nc]     = pack_hi(v.x, v.y);
                *(uint32_t*)&sBh[kr * SP_B + nc + 2] = pack_hi(v.z, v.w);
                *(uint32_t*)&sBl[kr * SP_B + nc]     = pack_lo(v.x, v.y);
                *(uint32_t*)&sBl[kr * SP_B + nc + 2] = pack_lo(v.z, v.w);
            }
        }
        __syncthreads();

        if (chunk + 1 < H / PROJ_BK) {
            const int k0n = (chunk + 1) * PROJ_BK;
            #pragma unroll
            for (int i = 0; i < 2; i++) {
                const int idx = t + i * 512;
                pa[i] = *(const float4*)&A[((m0 + (idx >> 3)) * H) + k0n + ((idx & 7) << 2)];
                pb[i] = *(const float4*)&W[((k0n + (idx >> 5)) * H) + n0 + ((idx & 31) << 2)];
            }
        }

        #pragma unroll
        for (int ks = 0; ks < 2; ks++) {
            const int kb = ks * 16;

            uint32_t ah[2][4], al[2][4];
            #pragma unroll
            for (int mt = 0; mt < 2; mt++) {
                const int row = wm + mt * 16 + (lane & 15);
                const int kc  = kb + ((lane >> 4) << 3);
                ldsm_x4(ah[mt], smem_u32(&sAh[row * SP_A + kc]));
                ldsm_x4(al[mt], smem_u32(&sAl[row * SP_A + kc]));
            }
            #pragma unroll
            for (int nt = 0; nt < 4; nt++) {
                uint32_t bh[2], bl[2];
                const int krow  = kb + (lane & 15);
                const int nbase = wn + nt * 8;
                ldsm_x2_trans(bh, smem_u32(&sBh[krow * SP_B + nbase]));
                ldsm_x2_trans(bl, smem_u32(&sBl[krow * SP_B + nbase]));
                #pragma unroll
                for (int mt = 0; mt < 2; mt++) {
                    mma_bf16(acc[mt][nt], ah[mt], bh);
                    mma_bf16(acc[mt][nt], al[mt], bh);
                    mma_bf16(acc[mt][nt], ah[mt], bl);
                }
            }
        }
        __syncthreads();
    }

    #pragma unroll
    for (int mt = 0; mt < 2; mt++) {
        const int r0 = m0 + wm + mt * 16 + (lane >> 2);
        #pragma unroll
        for (int nt = 0; nt < 4; nt++) {
            const int c0 = n0 + wn + nt * 8 + (lane & 3) * 2;
            *(float2*)&C[r0 * H + c0]       = make_float2(acc[mt][nt][0], acc[mt][nt][1]);
            *(float2*)&C[(r0 + 8) * H + c0] = make_float2(acc[mt][nt][2], acc[mt][nt][3]);
        }
    }
}

// ---------------------------------------------------------------------------
// Kernel 2: scores via f16x2 tanh, fp32 staging/accumulation.
// QI=32, 256 threads (8 warps x 4 rows) -> 3 CTAs/SM = 24 warps/SM (6/SMSP)
// for latency hiding. One CTA per (j-tile, b, q-tile); early exit past vl.
// ---------------------------------------------------------------------------
__global__ __launch_bounds__(256) void score_kernel(
    const int* __restrict__ valid_lens, const float* __restrict__ w_v)
{
    constexpr int QI = 32;
    constexpr int KJ = 32;
    constexpr int HP = H + 4;

    const int jt = blockIdx.x;
    const int b  = blockIdx.y;
    const int q0 = blockIdx.z * QI;
    const int j0 = jt * KJ;

    const int vl = __ldg(&valid_lens[b]);
    if (j0 >= vl) return;

    extern __shared__ float sm[];
    float* sq = sm;             // QI * HP
    float* sk = sq + QI * HP;   // KJ * HP
    float* sw = sk + KJ * HP;   // H

    const int t    = threadIdx.x;
    const int lane = t & 31;
    const int warp = t >> 5;    // 0..7

    for (int idx = t; idx < QI * (H / 4); idx += 256) {
        const int i  = idx >> 6;
        const int hc = (idx & 63) << 2;
        *(float4*)&sq[i * HP + hc] =
            *(const float4*)&g_q[(b * LQ + q0 + i) * H + hc];
    }
    for (int idx = t; idx < KJ * (H / 4); idx += 256) {
        const int j  = idx >> 6;
        const int hc = (idx & 63) << 2;
        *(float4*)&sk[j * HP + hc] =
            *(const float4*)&g_k[(b * LK + j0 + j) * H + hc];
    }
    if (t < H / 4) *(float4*)&sw[t * 4] = *(const float4*)&w_v[t * 4];
    __syncthreads();

    float a0 = 0.f, a1 = 0.f, a2 = 0.f, a3 = 0.f;
    const float* qp0 = &sq[(warp * 4 + 0) * HP];
    const float* qp1 = &sq[(warp * 4 + 1) * HP];
    const float* qp2 = &sq[(warp * 4 + 2) * HP];
    const float* qp3 = &sq[(warp * 4 + 3) * HP];
    const float* kp  = &sk[lane * HP];

    #pragma unroll 2
    for (int h = 0; h < H; h += 4) {
        float4 k4 = *(const float4*)&kp[h];
        float4 w4 = *(const float4*)&sw[h];

        {
            float4 qv = *(const float4*)&qp0[h];
            uint32_t p01 = pack_f16x2(qv.x + k4.x, qv.y + k4.y);
            uint32_t p23 = pack_f16x2(qv.z + k4.z, qv.w + k4.w);
            float2 t01 = unpack_f16x2(tanh2(p01));
            float2 t23 = unpack_f16x2(tanh2(p23));
            a0 += w4.x * t01.x; a0 += w4.y * t01.y;
            a0 += w4.z * t23.x; a0 += w4.w * t23.y;
        }
        {
            float4 qv = *(const float4*)&qp1[h];
            uint32_t p01 = pack_f16x2(qv.x + k4.x, qv.y + k4.y);
            uint32_t p23 = pack_f16x2(qv.z + k4.z, qv.w + k4.w);
            float2 t01 = unpack_f16x2(tanh2(p01));
            float2 t23 = unpack_f16x2(tanh2(p23));
            a1 += w4.x * t01.x; a1 += w4.y * t01.y;
            a1 += w4.z * t23.x; a1 += w4.w * t23.y;
        }
        {
            float4 qv = *(const float4*)&qp2[h];
            uint32_t p01 = pack_f16x2(qv.x + k4.x, qv.y + k4.y);
            uint32_t p23 = pack_f16x2(qv.z + k4.z, qv.w + k4.w);
            float2 t01 = unpack_f16x2(tanh2(p01));
            float2 t23 = unpack_f16x2(tanh2(p23));
            a2 += w4.x * t01.x; a2 += w4.y * t01.y;
            a2 += w4.z * t23.x; a2 += w4.w * t23.y;
        }
        {
            float4 qv = *(const float4*)&qp3[h];
            uint32_t p01 = pack_f16x2(qv.x + k4.x, qv.y + k4.y);
            uint32_t p23 = pack_f16x2(qv.z + k4.z, qv.w + k4.w);
            float2 t01 = unpack_f16x2(tanh2(p01));
            float2 t23 = unpack_f16x2(tanh2(p23));
            a3 += w4.x * t01.x; a3 += w4.y * t01.y;
            a3 += w4.z * t23.x; a3 += w4.w * t23.y;
        }
    }

    const int rbase = b * LQ + q0 + warp * 4;
    g_s[(rbase + 0) * LK + j0 + lane] = a0;
    g_s[(rbase + 1) * LK + j0 + lane] = a1;
    g_s[(rbase + 2) * LK + j0 + lane] = a2;
    g_s[(rbase + 3) * LK + j0 + lane] = a3;
}

// ---------------------------------------------------------------------------
// Kernel 3: masked softmax over j + out = P @ V
// QI=16 rows per CTA, 256 threads. Stages only columns j < valid_len.
// ---------------------------------------------------------------------------
__global__ __launch_bounds__(256) void softpv_kernel(
    const float* __restrict__ values, const int* __restrict__ valid_lens,
    float* __restrict__ out)
{
    constexpr int QI = 16;
    __shared__ float sp[QI * LK];

    const int b    = blockIdx.x;
    const int q0   = blockIdx.y * QI;
    const int t    = threadIdx.x;
    const int lane = t & 31;
    const int warp = t >> 5;          // 0..7

    const int vl = valid_lens[b];

    for (int idx = t; idx < QI * (LK / 4); idx += 256) {
        const int i  = idx >> 6;
        const int jc = (idx & 63) << 2;
        if (jc < vl)
            *(float4*)&sp[i * LK + jc] =
                *(const float4*)&g_s[(b * LQ + q0 + i) * LK + jc];
    }
    __syncthreads();

    #pragma unroll
    for (int rr = 0; rr < 2; rr++) {
        const int r = warp + rr * 8;
        float* row = &sp[r * LK];

        float m = -1e30f;
        for (int j = lane; j < LK; j += 32) {
            float s = (j < vl) ? row[j] : -1e30f;
            m = fmaxf(m, s);
        }
        #pragma unroll
        for (int o = 16; o; o >>= 1) m = fmaxf(m, __shfl_xor_sync(0xffffffffu, m, o));

        float ssum = 0.f;
        for (int j = lane; j < LK; j += 32) {
            float e = (j < vl) ? __expf(row[j] - m) : 0.f;
            row[j] = e;
            ssum += e;
        }
        #pragma unroll
        for (int o = 16; o; o >>= 1) ssum += __shfl_xor_sync(0xffffffffu, ssum, o);

        const float inv = 1.0f / ssum;
        for (int j = lane; j < LK; j += 32) row[j] *= inv;
    }
    __syncthreads();

    const int ig = (t >> 6) * 4;        // 0,4,8,12
    const int v0 = (t & 63) * 4;        // 0..252
    float acc[4][4] = {};
    const float* vb = &values[b * LK * H];

    const int jend = min(LK, (vl + 3) & ~3);
    for (int j = 0; j < jend; j += 4) {
        float vvf[4][4];
        #pragma unroll
        for (int jj = 0; jj < 4; jj++) {
            float4 tmp = *(const float4*)&vb[(j + jj) * H + v0];
            vvf[jj][0] = tmp.x; vvf[jj][1] = tmp.y; vvf[jj][2] = tmp.z; vvf[jj][3] = tmp.w;
        }
        #pragma unroll
        for (int r = 0; r < 4; r++) {
            float4 p = *(const float4*)&sp[(ig + r) * LK + j];
            #pragma unroll
            for (int c = 0; c < 4; c++) {
                acc[r][c] += p.x * vvf[0][c];
                acc[r][c] += p.y * vvf[1][c];
                acc[r][c] += p.z * vvf[2][c];
                acc[r][c] += p.w * vvf[3][c];
            }
        }
    }

    #pragma unroll
    for (int r = 0; r < 4; r++) {
        float4 o = make_float4(acc[r][0], acc[r][1], acc[r][2], acc[r][3]);
        *(float4*)&out[(b * LQ + q0 + ig + r) * H + v0] = o;
    }
}

// ---------------------------------------------------------------------------
extern "C" void kernel_launch(void* const* d_in, const int* in_sizes, int n_in,
                              void* d_out, int out_size) {
    (void)in_sizes; (void)n_in; (void)out_size;
    const float* queries = (const float*)d_in[0];
    const float* keys    = (const float*)d_in[1];
    const float* values  = (const float*)d_in[2];
    const int*   vlens   = (const int*)d_in[3];
    const float* Wq      = (const float*)d_in[4];
    const float* Wk      = (const float*)d_in[5];
    const float* wv      = (const float*)d_in[6];
    float* out = (float*)d_out;

    cudaFuncSetAttribute(proj_mma_kernel,
                         cudaFuncAttributeMaxDynamicSharedMemorySize, PROJ_SMEM_BYTES);
    dim3 pg((NB * LQ) / PROJ_BM, H / PROJ_BN, 2);   // 128 CTAs
    proj_mma_kernel<<<pg, 512, PROJ_SMEM_BYTES>>>(queries, keys, Wq, Wk, vlens);

    constexpr int QI = 32, KJ = 32, HP = H + 4;
    constexpr int SMEM = (QI * HP + KJ * HP + H) * (int)sizeof(float);  // ~67.6KB
    cudaFuncSetAttribute(score_kernel, cudaFuncAttributeMaxDynamicSharedMemorySize, SMEM);
    dim3 sg(LK / KJ, NB, LQ / QI);   // 8 x 16 x 8 = 1024 CTAs
    score_kernel<<<sg, 256, SMEM>>>(vlens, wv);

    dim3 og(NB, LQ / 16);            // 256 CTAs
    softpv_kernel<<<og, 256>>>(values, vlens, out);
}